// round 11
// baseline (speedup 1.0000x reference)
#include <cuda_runtime.h>
#include <cuda_fp16.h>
#include <cstdint>

// Problem shape (fixed): B=32, Q=512, K=512, D=1024
#define NB   32
#define NQ   512
#define NK   512
#define ND   1024

#define BM 128
#define BN 128
#define KC 32                  // K elements per chunk
#define NCHUNK (ND / KC)       // 32
#define THREADS 512
#define NSTAGE 3

// SMEM tile geometry: fp16 plane = 128 rows x 32 halfs (64B data) padded to 80B
#define ROWB    80
#define PLANE_B (128 * ROWB)          // 10240
#define STAGE_B (4 * PLANE_B)         // 40960  (Ahi | Alo | Bhi | Blo)
#define SMEM_BYTES (NSTAGE * STAGE_B) // 122880

#define NEG_INF  (__int_as_float(0xff800000))
#define INV2048  4.8828125e-4f

// ---------------------------------------------------------------------------
// device scratch (no allocation in kernel_launch)
// ---------------------------------------------------------------------------
#define ELEMS (NB * NQ * ND)   // 16777216 per tensor
__device__ __align__(16) __half g_Qh[ELEMS];
__device__ __align__(16) __half g_Ql[ELEMS];
__device__ __align__(16) __half g_Kh[ELEMS];
__device__ __align__(16) __half g_Kl[ELEMS];
__device__ uint32_t g_mask[NB * (NK / 32)];    // key-mask bitmaps

// ---------------------------------------------------------------------------
// helpers
// ---------------------------------------------------------------------------
__device__ __forceinline__ uint32_t smem_u32(const void* p) {
    uint32_t a;
    asm("{ .reg .u64 t; cvta.to.shared.u64 t, %1; cvt.u32.u64 %0, t; }"
        : "=r"(a) : "l"(p));
    return a;
}

#define CP_ASYNC16(dst, src) \
    asm volatile("cp.async.cg.shared.global [%0], [%1], 16;" :: "r"(dst), "l"(src))
#define CP_COMMIT() asm volatile("cp.async.commit_group;" ::: "memory")
#define CP_WAIT1()  asm volatile("cp.async.wait_group 1;" ::: "memory")

#define LDSM4(r0, r1, r2, r3, a)                                                \
    asm volatile("ldmatrix.sync.aligned.m8n8.x4.shared.b16 {%0,%1,%2,%3}, [%4];" \
                 : "=r"(r0), "=r"(r1), "=r"(r2), "=r"(r3) : "r"(a))

// fp32-accumulate MMA (main hi x hi pass)
#define MMA_F32(c, a0, a1, a2, a3, b0, b1)                                       \
    asm volatile(                                                                \
        "mma.sync.aligned.m16n8k16.row.col.f32.f16.f16.f32 "                     \
        "{%0,%1,%2,%3}, {%4,%5,%6,%7}, {%8,%9}, {%0,%1,%2,%3};"                  \
        : "+f"((c)[0]), "+f"((c)[1]), "+f"((c)[2]), "+f"((c)[3])                 \
        : "r"(a0), "r"(a1), "r"(a2), "r"(a3), "r"(b0), "r"(b1))

// fp16-accumulate MMA (correction passes, accumulated unscaled)
#define MMA_F16(c, a0, a1, a2, a3, b0, b1)                                       \
    asm volatile(                                                                \
        "mma.sync.aligned.m16n8k16.row.col.f16.f16.f16.f16 "                     \
        "{%0,%1}, {%2,%3,%4,%5}, {%6,%7}, {%0,%1};"                              \
        : "+r"((c)[0]), "+r"((c)[1])                                             \
        : "r"(a0), "r"(a1), "r"(a2), "r"(a3), "r"(b0), "r"(b1))

// ---------------------------------------------------------------------------
// Kernel 0: streaming fp32 -> (hi fp16, lo' fp16 = (x-hi)*2048) split.
// ---------------------------------------------------------------------------
__global__ __launch_bounds__(256)
void convert_kernel(const float* __restrict__ src,
                    __half* __restrict__ hi,
                    __half* __restrict__ lo)
{
    const size_t i = ((size_t)blockIdx.x * 256 + threadIdx.x) * 8;
    float4 a = *(const float4*)(src + i);
    float4 b = *(const float4*)(src + i + 4);

    __half2 h0 = __floats2half2_rn(a.x, a.y);
    __half2 h1 = __floats2half2_rn(a.z, a.w);
    __half2 h2 = __floats2half2_rn(b.x, b.y);
    __half2 h3 = __floats2half2_rn(b.z, b.w);

    __half2 l0 = __floats2half2_rn((a.x - __low2float(h0)) * 2048.0f,
                                   (a.y - __high2float(h0)) * 2048.0f);
    __half2 l1 = __floats2half2_rn((a.z - __low2float(h1)) * 2048.0f,
                                   (a.w - __high2float(h1)) * 2048.0f);
    __half2 l2 = __floats2half2_rn((b.x - __low2float(h2)) * 2048.0f,
                                   (b.y - __high2float(h2)) * 2048.0f);
    __half2 l3 = __floats2half2_rn((b.z - __low2float(h3)) * 2048.0f,
                                   (b.w - __high2float(h3)) * 2048.0f);

    *(uint4*)(hi + i) = make_uint4(*(uint32_t*)&h0, *(uint32_t*)&h1,
                                   *(uint32_t*)&h2, *(uint32_t*)&h3);
    *(uint4*)(lo + i) = make_uint4(*(uint32_t*)&l0, *(uint32_t*)&l1,
                                   *(uint32_t*)&l2, *(uint32_t*)&l3);
}

// ---------------------------------------------------------------------------
// Kernel 0b: key-mask bitmap (keys[b,k,0] == 0)
// ---------------------------------------------------------------------------
__global__ __launch_bounds__(512)
void mask_kernel(const float* __restrict__ keys, uint32_t* __restrict__ mask)
{
    const int b = blockIdx.x;
    const int k = threadIdx.x;
    const float k0 = __ldg(keys + (size_t)b * NK * ND + (size_t)k * ND);
    const uint32_t bits = __ballot_sync(0xffffffffu, k0 == 0.0f);
    if ((k & 31) == 0) mask[b * (NK / 32) + (k >> 5)] = bits;
}

// ---------------------------------------------------------------------------
// Kernel 1: batched NT GEMM, fp32 emulated via fp16 mma.sync (3 passes).
// 128x128 CTA tile, 512 threads / 16 warps, warp tile 32x32,
// 3-stage cp.async pipeline, ldmatrix fragment loads.
// ---------------------------------------------------------------------------
__global__ __launch_bounds__(THREADS, 1)
void gemm_hmma_kernel(float* __restrict__ C)
{
    extern __shared__ __align__(16) char smem[];
    const uint32_t sb = smem_u32(smem);

    const int tid  = threadIdx.x;
    const int wid  = tid >> 5;
    const int lane = tid & 31;
    const int gid  = lane >> 2;
    const int tig  = lane & 3;

    const int wm = wid & 3;           // 0..3 -> 32-row band
    const int wn = wid >> 2;          // 0..3 -> 32-col band

    const int b  = blockIdx.z;
    const int m0 = blockIdx.y * BM;
    const int n0 = blockIdx.x * BN;

    const size_t Aoff = (size_t)b * NQ * ND + (size_t)m0 * ND;
    const size_t Boff = (size_t)b * NK * ND + (size_t)n0 * ND;
    float* Cb = C + (size_t)b * NQ * NK;

    const __half* pb[4] = { g_Qh + Aoff, g_Ql + Aoff, g_Kh + Boff, g_Kl + Boff };

    // cp.async geometry: 4 issues/thread, one per plane
    const int rA  = tid >> 2;        // 0..127
    const int c16 = tid & 3;         // 16B column within 64B row

    // ldmatrix per-lane addressing
    const int arow_lane = wm * 32 + (lane & 15);
    const uint32_t akh  = (uint32_t)((lane >> 4) * 16);
    const int brow_lane = wn * 32 + ((lane >> 4) * 8) + (lane & 7);
    const uint32_t bkh  = (uint32_t)(((lane >> 3) & 1) * 16);

    float acc[2][4][4];
    uint32_t acc16[2][4][2];
#pragma unroll
    for (int i = 0; i < 2; i++)
#pragma unroll
        for (int j = 0; j < 4; j++) {
#pragma unroll
            for (int k = 0; k < 4; k++) acc[i][j][k] = 0.0f;
            acc16[i][j][0] = 0u; acc16[i][j][1] = 0u;
        }

    auto issue_stage = [&](int kc, int buf) {
        const uint32_t sdst = sb + buf * STAGE_B;
#pragma unroll
        for (int p = 0; p < 4; p++) {
            const __half* src = pb[p] + (size_t)rA * ND + kc * KC + c16 * 8;
            const uint32_t dst = sdst + p * PLANE_B + rA * ROWB + c16 * 16;
            CP_ASYNC16(dst, src);
        }
    };

    issue_stage(0, 0); CP_COMMIT();
    issue_stage(1, 1); CP_COMMIT();

    for (int kc = 0; kc < NCHUNK; kc++) {
        const int buf = kc % NSTAGE;
        CP_WAIT1();
        __syncthreads();

        if (kc + 2 < NCHUNK) issue_stage(kc + 2, (kc + 2) % NSTAGE);
        CP_COMMIT();

        const uint32_t st   = sb + buf * STAGE_B;
        const uint32_t stA  = st;                    // Ahi
        const uint32_t stAl = st + PLANE_B;          // Alo'
        const uint32_t stB  = st + 2 * PLANE_B;      // Bhi
        const uint32_t stBl = st + 3 * PLANE_B;      // Blo'

#pragma unroll
        for (int ks = 0; ks < 2; ks++) {
            const uint32_t kofs = ks * 32;

            uint32_t ah[2][4], bh[4][2];
#pragma unroll
            for (int mt = 0; mt < 2; mt++) {
                const uint32_t a = stA + (arow_lane + mt * 16) * ROWB + akh + kofs;
                LDSM4(ah[mt][0], ah[mt][1], ah[mt][2], ah[mt][3], a);
            }
#pragma unroll
            for (int ntp = 0; ntp < 2; ntp++) {
                const uint32_t a = stB + (brow_lane + ntp * 16) * ROWB + bkh + kofs;
                LDSM4(bh[2 * ntp][0], bh[2 * ntp][1],
                      bh[2 * ntp + 1][0], bh[2 * ntp + 1][1], a);
            }
            // pass 1: hi x hi -> fp32 acc
#pragma unroll
            for (int mt = 0; mt < 2; mt++)
#pragma unroll
                for (int nt = 0; nt < 4; nt++)
                    MMA_F32(acc[mt][nt], ah[mt][0], ah[mt][1], ah[mt][2], ah[mt][3],
                            bh[nt][0], bh[nt][1]);

            // pass 2: hi_a x lo'_b -> fp16 acc (unscaled)
            uint32_t bl[4][2];
#pragma unroll
            for (int ntp = 0; ntp < 2; ntp++) {
                const uint32_t a = stBl + (brow_lane + ntp * 16) * ROWB + bkh + kofs;
                LDSM4(bl[2 * ntp][0], bl[2 * ntp][1],
                      bl[2 * ntp + 1][0], bl[2 * ntp + 1][1], a);
            }
#pragma unroll
            for (int mt = 0; mt < 2; mt++)
#pragma unroll
                for (int nt = 0; nt < 4; nt++)
                    MMA_F16(acc16[mt][nt], ah[mt][0], ah[mt][1], ah[mt][2], ah[mt][3],
                            bl[nt][0], bl[nt][1]);

            // pass 3: lo'_a x hi_b -> fp16 acc
            uint32_t al[2][4];
#pragma unroll
            for (int mt = 0; mt < 2; mt++) {
                const uint32_t a = stAl + (arow_lane + mt * 16) * ROWB + akh + kofs;
                LDSM4(al[mt][0], al[mt][1], al[mt][2], al[mt][3], a);
            }
#pragma unroll
            for (int mt = 0; mt < 2; mt++)
#pragma unroll
                for (int nt = 0; nt < 4; nt++)
                    MMA_F16(acc16[mt][nt], al[mt][0], al[mt][1], al[mt][2], al[mt][3],
                            bh[nt][0], bh[nt][1]);
        }
        __syncthreads();
    }

    // epilogue: combine fp32 main + fp16 correction * 2^-11
#pragma unroll
    for (int mt = 0; mt < 2; mt++) {
        const int mrow = m0 + wm * 32 + mt * 16 + gid;
#pragma unroll
        for (int nt = 0; nt < 4; nt++) {
            const int col = n0 + wn * 32 + nt * 8 + tig * 2;
            float2 c0 = __half22float2(*reinterpret_cast<__half2*>(&acc16[mt][nt][0]));
            float2 c1 = __half22float2(*reinterpret_cast<__half2*>(&acc16[mt][nt][1]));
            float* cp0 = Cb + (size_t)mrow * NK + col;
            float* cp1 = Cb + (size_t)(mrow + 8) * NK + col;
            *(float2*)cp0 = make_float2(fmaf(c0.x, INV2048, acc[mt][nt][0]),
                                        fmaf(c0.y, INV2048, acc[mt][nt][1]));
            *(float2*)cp1 = make_float2(fmaf(c1.x, INV2048, acc[mt][nt][2]),
                                        fmaf(c1.y, INV2048, acc[mt][nt][3]));
        }
    }
}

// ---------------------------------------------------------------------------
// Kernel 2: fused key-mask + softmax + logsumexp->sigmoid confidence.
// One warp per (b,q) row; mask from precomputed bitmap; float4 row I/O.
// ---------------------------------------------------------------------------
__global__ __launch_bounds__(256)
void softmax_mask_kernel(float* __restrict__ attn,
                         float* __restrict__ conf,
                         const uint32_t* __restrict__ maskbits,
                         const float* __restrict__ tptr,
                         const float* __restrict__ bptr,
                         int writeConf)
{
    __shared__ uint32_t mw[NK / 32];

    const int lane = threadIdx.x & 31;
    const int w    = threadIdx.x >> 5;
    const int row0 = blockIdx.x * 8;
    const int b    = row0 >> 9;

    if (threadIdx.x < NK / 32)
        mw[threadIdx.x] = maskbits[b * (NK / 32) + threadIdx.x];
    __syncthreads();

    const int row = row0 + w;
    float4* rp4 = (float4*)(attn + (size_t)row * NK);

    float x[16];
#pragma unroll
    for (int i = 0; i < 4; i++) {
        float4 v = rp4[i * 32 + lane];
        const int cbase = (i * 32 + lane) * 4;
        const uint32_t nib = (mw[cbase >> 5] >> (cbase & 31)) & 0xF;
        x[4 * i + 0] = (nib & 1) ? NEG_INF : v.x;
        x[4 * i + 1] = (nib & 2) ? NEG_INF : v.y;
        x[4 * i + 2] = (nib & 4) ? NEG_INF : v.z;
        x[4 * i + 3] = (nib & 8) ? NEG_INF : v.w;
    }

    float m = x[0];
#pragma unroll
    for (int i = 1; i < 16; i++) m = fmaxf(m, x[i]);
#pragma unroll
    for (int o = 16; o > 0; o >>= 1)
        m = fmaxf(m, __shfl_xor_sync(0xffffffffu, m, o));

    float e[16];
    float sum = 0.0f;
#pragma unroll
    for (int i = 0; i < 16; i++) {
        e[i] = __expf(x[i] - m);
        sum += e[i];
    }
#pragma unroll
    for (int o = 16; o > 0; o >>= 1)
        sum += __shfl_xor_sync(0xffffffffu, sum, o);

    const float inv = 1.0f / sum;
#pragma unroll
    for (int i = 0; i < 4; i++) {
        float4 o;
        o.x = e[4 * i + 0] * inv;
        o.y = e[4 * i + 1] * inv;
        o.z = e[4 * i + 2] * inv;
        o.w = e[4 * i + 3] * inv;
        rp4[i * 32 + lane] = o;
    }

    if (lane == 0 && writeConf) {
        const float lse  = m + __logf(sum);
        const float temp = *tptr;
        const float bia  = *bptr;
        const float z    = (lse + bia) * temp;
        conf[row] = 1.0f / (1.0f + __expf(-z));
    }
}

// ---------------------------------------------------------------------------
extern "C" void kernel_launch(void* const* d_in, const int* in_sizes, int n_in,
                              void* d_out, int out_size)
{
    const float* q  = (const float*)d_in[0];
    const float* k  = (const float*)d_in[1];
    const float* t  = (const float*)d_in[2];
    const float* bi = (const float*)d_in[3];

    float* attn = (float*)d_out;
    const long long attnElems = (long long)NB * NQ * NK;       // 8388608
    const int writeConf = (out_size >= attnElems + NB * NQ) ? 1 : 0;
    float* conf = attn + attnElems;

    static int smemSet = 0;
    if (!smemSet) {
        cudaFuncSetAttribute(gemm_hmma_kernel,
                             cudaFuncAttributeMaxDynamicSharedMemorySize, SMEM_BYTES);
        smemSet = 1;
    }

    static __half *Qh = nullptr, *Ql = nullptr, *Kh = nullptr, *Kl = nullptr;
    static uint32_t* Mb = nullptr;
    if (!Qh) {
        cudaGetSymbolAddress((void**)&Qh, g_Qh);
        cudaGetSymbolAddress((void**)&Ql, g_Ql);
        cudaGetSymbolAddress((void**)&Kh, g_Kh);
        cudaGetSymbolAddress((void**)&Kl, g_Kl);
        cudaGetSymbolAddress((void**)&Mb, g_mask);
    }

    convert_kernel<<<ELEMS / (256 * 8), 256>>>(q, Qh, Ql);
    convert_kernel<<<ELEMS / (256 * 8), 256>>>(k, Kh, Kl);
    mask_kernel<<<NB, 512>>>(k, Mb);

    dim3 grid(NK / BN, NQ / BM, NB);        // (4, 4, 32)
    gemm_hmma_kernel<<<grid, THREADS, SMEM_BYTES>>>(attn);

    softmax_mask_kernel<<<(NB * NQ) / 8, 256>>>(attn, conf, Mb, t, bi, writeConf);
}

// round 16
// speedup vs baseline: 1.1903x; 1.1903x over previous
#include <cuda_runtime.h>
#include <cuda_fp16.h>
#include <cstdint>

// Problem shape (fixed): B=32, Q=512, K=512, D=1024
#define NB   32
#define NQ   512
#define NK   512
#define ND   1024

#define BM 128
#define BN 128
#define KC 64                  // K elements per chunk
#define NCHUNK (ND / KC)       // 16
#define THREADS 256
#define NSTAGE 3

// SMEM tile geometry: fp16 plane = 128 rows x 64 halfs (128B data) padded to 144B
#define ROWB    144
#define PLANE_B (128 * ROWB)          // 18432
#define STAGE_B (4 * PLANE_B)         // 73728  (Ahi | Alo | Bhi | Blo)
#define SMEM_BYTES (NSTAGE * STAGE_B) // 221184

#define NEG_INF  (__int_as_float(0xff800000))
#define INV2048  4.8828125e-4f

// ---------------------------------------------------------------------------
// device scratch (no allocation in kernel_launch)
// ---------------------------------------------------------------------------
#define ELEMS (NB * NQ * ND)   // 16777216 per tensor
__device__ __align__(16) __half g_Qh[ELEMS];
__device__ __align__(16) __half g_Ql[ELEMS];
__device__ __align__(16) __half g_Kh[ELEMS];
__device__ __align__(16) __half g_Kl[ELEMS];
__device__ uint32_t g_mask[NB * (NK / 32)];    // key-mask bitmaps

// ---------------------------------------------------------------------------
// helpers
// ---------------------------------------------------------------------------
__device__ __forceinline__ uint32_t smem_u32(const void* p) {
    uint32_t a;
    asm("{ .reg .u64 t; cvta.to.shared.u64 t, %1; cvt.u32.u64 %0, t; }"
        : "=r"(a) : "l"(p));
    return a;
}

#define CP_ASYNC16(dst, src) \
    asm volatile("cp.async.cg.shared.global [%0], [%1], 16;" :: "r"(dst), "l"(src))
#define CP_COMMIT() asm volatile("cp.async.commit_group;" ::: "memory")
#define CP_WAIT1()  asm volatile("cp.async.wait_group 1;" ::: "memory")

#define LDSM4(r0, r1, r2, r3, a)                                                \
    asm volatile("ldmatrix.sync.aligned.m8n8.x4.shared.b16 {%0,%1,%2,%3}, [%4];" \
                 : "=r"(r0), "=r"(r1), "=r"(r2), "=r"(r3) : "r"(a))

// fp32-accumulate MMA (main hi x hi pass)
#define MMA_F32(c, a0, a1, a2, a3, b0, b1)                                       \
    asm volatile(                                                                \
        "mma.sync.aligned.m16n8k16.row.col.f32.f16.f16.f32 "                     \
        "{%0,%1,%2,%3}, {%4,%5,%6,%7}, {%8,%9}, {%0,%1,%2,%3};"                  \
        : "+f"((c)[0]), "+f"((c)[1]), "+f"((c)[2]), "+f"((c)[3])                 \
        : "r"(a0), "r"(a1), "r"(a2), "r"(a3), "r"(b0), "r"(b1))

// fp16-accumulate MMA (correction passes, accumulated unscaled)
#define MMA_F16(c, a0, a1, a2, a3, b0, b1)                                       \
    asm volatile(                                                                \
        "mma.sync.aligned.m16n8k16.row.col.f16.f16.f16.f16 "                     \
        "{%0,%1}, {%2,%3,%4,%5}, {%6,%7}, {%0,%1};"                              \
        : "+r"((c)[0]), "+r"((c)[1])                                             \
        : "r"(a0), "r"(a1), "r"(a2), "r"(a3), "r"(b0), "r"(b1))

// ---------------------------------------------------------------------------
// Kernel 0: streaming fp32 -> (hi fp16, lo' fp16 = (x-hi)*2048) split.
// ---------------------------------------------------------------------------
__global__ __launch_bounds__(256)
void convert_kernel(const float* __restrict__ src,
                    __half* __restrict__ hi,
                    __half* __restrict__ lo)
{
    const size_t i = ((size_t)blockIdx.x * 256 + threadIdx.x) * 8;
    float4 a = *(const float4*)(src + i);
    float4 b = *(const float4*)(src + i + 4);

    __half2 h0 = __floats2half2_rn(a.x, a.y);
    __half2 h1 = __floats2half2_rn(a.z, a.w);
    __half2 h2 = __floats2half2_rn(b.x, b.y);
    __half2 h3 = __floats2half2_rn(b.z, b.w);

    __half2 l0 = __floats2half2_rn((a.x - __low2float(h0)) * 2048.0f,
                                   (a.y - __high2float(h0)) * 2048.0f);
    __half2 l1 = __floats2half2_rn((a.z - __low2float(h1)) * 2048.0f,
                                   (a.w - __high2float(h1)) * 2048.0f);
    __half2 l2 = __floats2half2_rn((b.x - __low2float(h2)) * 2048.0f,
                                   (b.y - __high2float(h2)) * 2048.0f);
    __half2 l3 = __floats2half2_rn((b.z - __low2float(h3)) * 2048.0f,
                                   (b.w - __high2float(h3)) * 2048.0f);

    *(uint4*)(hi + i) = make_uint4(*(uint32_t*)&h0, *(uint32_t*)&h1,
                                   *(uint32_t*)&h2, *(uint32_t*)&h3);
    *(uint4*)(lo + i) = make_uint4(*(uint32_t*)&l0, *(uint32_t*)&l1,
                                   *(uint32_t*)&l2, *(uint32_t*)&l3);
}

// ---------------------------------------------------------------------------
// Kernel 0b: key-mask bitmap (keys[b,k,0] == 0)
// ---------------------------------------------------------------------------
__global__ __launch_bounds__(512)
void mask_kernel(const float* __restrict__ keys, uint32_t* __restrict__ mask)
{
    const int b = blockIdx.x;
    const int k = threadIdx.x;
    const float k0 = __ldg(keys + (size_t)b * NK * ND + (size_t)k * ND);
    const uint32_t bits = __ballot_sync(0xffffffffu, k0 == 0.0f);
    if ((k & 31) == 0) mask[b * (NK / 32) + (k >> 5)] = bits;
}

// ---------------------------------------------------------------------------
// Kernel 1: batched NT GEMM, fp32 emulated via fp16 mma.sync (3 passes).
// 128x128 CTA tile, 256 threads / 8 warps, warp tile 64x32,
// KC=64 chunks (16 barrier windows), 3-stage cp.async pipeline,
// all ldmatrix loads of a k-step batched ahead of its MMAs.
// ---------------------------------------------------------------------------
__global__ __launch_bounds__(THREADS, 1)
void gemm_hmma_kernel(float* __restrict__ C)
{
    extern __shared__ __align__(16) char smem[];
    const uint32_t sb = smem_u32(smem);

    const int tid  = threadIdx.x;
    const int wid  = tid >> 5;
    const int lane = tid & 31;
    const int gid  = lane >> 2;
    const int tig  = lane & 3;

    const int wm = wid & 1;           // 0..1 -> 64-row band
    const int wn = wid >> 1;          // 0..3 -> 32-col band

    const int b  = blockIdx.z;
    const int m0 = blockIdx.y * BM;
    const int n0 = blockIdx.x * BN;

    const size_t Aoff = (size_t)b * NQ * ND + (size_t)m0 * ND;
    const size_t Boff = (size_t)b * NK * ND + (size_t)n0 * ND;
    float* Cb = C + (size_t)b * NQ * NK;

    const __half* pb[4] = { g_Qh + Aoff, g_Ql + Aoff, g_Kh + Boff, g_Kl + Boff };

    // cp.async geometry: 16 issues/thread/stage (4 per plane)
    // f = tid + j*256 ; row = f>>3 (0..127), c16 = f&7 (16B col within 128B row)
    const int rbase = tid >> 3;
    const int cbase = tid & 7;

    // ldmatrix per-lane addressing
    const int arow_lane = wm * 64 + (lane & 15);
    const uint32_t akh  = (uint32_t)((lane >> 4) * 16);
    const int brow_lane = wn * 32 + ((lane >> 4) * 8) + (lane & 7);
    const uint32_t bkh  = (uint32_t)(((lane >> 3) & 1) * 16);

    float acc[4][4][4];
    uint32_t acc16[4][4][2];
#pragma unroll
    for (int i = 0; i < 4; i++)
#pragma unroll
        for (int j = 0; j < 4; j++) {
#pragma unroll
            for (int k = 0; k < 4; k++) acc[i][j][k] = 0.0f;
            acc16[i][j][0] = 0u; acc16[i][j][1] = 0u;
        }

    auto issue_stage = [&](int kc, int buf) {
        const uint32_t sdst = sb + buf * STAGE_B;
#pragma unroll
        for (int p = 0; p < 4; p++) {
#pragma unroll
            for (int j = 0; j < 4; j++) {
                const int row = rbase + j * 32;
                const __half* src = pb[p] + (size_t)row * ND + kc * KC + cbase * 8;
                const uint32_t dst = sdst + p * PLANE_B + row * ROWB + cbase * 16;
                CP_ASYNC16(dst, src);
            }
        }
    };

    issue_stage(0, 0); CP_COMMIT();
    issue_stage(1, 1); CP_COMMIT();

    for (int kc = 0; kc < NCHUNK; kc++) {
        const int buf = kc % NSTAGE;
        CP_WAIT1();
        __syncthreads();

        if (kc + 2 < NCHUNK) issue_stage(kc + 2, (kc + 2) % NSTAGE);
        CP_COMMIT();

        const uint32_t st   = sb + buf * STAGE_B;
        const uint32_t stA  = st;                    // Ahi
        const uint32_t stAl = st + PLANE_B;          // Alo'
        const uint32_t stB  = st + 2 * PLANE_B;      // Bhi
        const uint32_t stBl = st + 3 * PLANE_B;      // Blo'

#pragma unroll
        for (int ks = 0; ks < 4; ks++) {
            const uint32_t kofs = ks * 32;           // 16 halfs per k-step

            // ---- batch ALL fragment loads for this k-step up front ----
            uint32_t ah[4][4], al[4][4], bh[4][2], bl[4][2];
#pragma unroll
            for (int mt = 0; mt < 4; mt++) {
                const uint32_t a = stA + (arow_lane + mt * 16) * ROWB + akh + kofs;
                LDSM4(ah[mt][0], ah[mt][1], ah[mt][2], ah[mt][3], a);
            }
#pragma unroll
            for (int ntp = 0; ntp < 2; ntp++) {
                const uint32_t a = stB + (brow_lane + ntp * 16) * ROWB + bkh + kofs;
                LDSM4(bh[2 * ntp][0], bh[2 * ntp][1],
                      bh[2 * ntp + 1][0], bh[2 * ntp + 1][1], a);
            }
#pragma unroll
            for (int ntp = 0; ntp < 2; ntp++) {
                const uint32_t a = stBl + (brow_lane + ntp * 16) * ROWB + bkh + kofs;
                LDSM4(bl[2 * ntp][0], bl[2 * ntp][1],
                      bl[2 * ntp + 1][0], bl[2 * ntp + 1][1], a);
            }
#pragma unroll
            for (int mt = 0; mt < 4; mt++) {
                const uint32_t a = stAl + (arow_lane + mt * 16) * ROWB + akh + kofs;
                LDSM4(al[mt][0], al[mt][1], al[mt][2], al[mt][3], a);
            }

            // pass 1: hi x hi -> fp32 acc
#pragma unroll
            for (int mt = 0; mt < 4; mt++)
#pragma unroll
                for (int nt = 0; nt < 4; nt++)
                    MMA_F32(acc[mt][nt], ah[mt][0], ah[mt][1], ah[mt][2], ah[mt][3],
                            bh[nt][0], bh[nt][1]);

            // pass 2: hi_a x lo'_b -> fp16 acc (unscaled)
#pragma unroll
            for (int mt = 0; mt < 4; mt++)
#pragma unroll
                for (int nt = 0; nt < 4; nt++)
                    MMA_F16(acc16[mt][nt], ah[mt][0], ah[mt][1], ah[mt][2], ah[mt][3],
                            bl[nt][0], bl[nt][1]);

            // pass 3: lo'_a x hi_b -> fp16 acc
#pragma unroll
            for (int mt = 0; mt < 4; mt++)
#pragma unroll
                for (int nt = 0; nt < 4; nt++)
                    MMA_F16(acc16[mt][nt], al[mt][0], al[mt][1], al[mt][2], al[mt][3],
                            bh[nt][0], bh[nt][1]);
        }
        __syncthreads();
    }

    // epilogue: combine fp32 main + fp16 correction * 2^-11
#pragma unroll
    for (int mt = 0; mt < 4; mt++) {
        const int mrow = m0 + wm * 64 + mt * 16 + gid;
#pragma unroll
        for (int nt = 0; nt < 4; nt++) {
            const int col = n0 + wn * 32 + nt * 8 + tig * 2;
            float2 c0 = __half22float2(*reinterpret_cast<__half2*>(&acc16[mt][nt][0]));
            float2 c1 = __half22float2(*reinterpret_cast<__half2*>(&acc16[mt][nt][1]));
            float* cp0 = Cb + (size_t)mrow * NK + col;
            float* cp1 = Cb + (size_t)(mrow + 8) * NK + col;
            *(float2*)cp0 = make_float2(fmaf(c0.x, INV2048, acc[mt][nt][0]),
                                        fmaf(c0.y, INV2048, acc[mt][nt][1]));
            *(float2*)cp1 = make_float2(fmaf(c1.x, INV2048, acc[mt][nt][2]),
                                        fmaf(c1.y, INV2048, acc[mt][nt][3]));
        }
    }
}

// ---------------------------------------------------------------------------
// Kernel 2: fused key-mask + softmax + logsumexp->sigmoid confidence.
// One warp per (b,q) row; mask from precomputed bitmap; float4 row I/O.
// ---------------------------------------------------------------------------
__global__ __launch_bounds__(256)
void softmax_mask_kernel(float* __restrict__ attn,
                         float* __restrict__ conf,
                         const uint32_t* __restrict__ maskbits,
                         const float* __restrict__ tptr,
                         const float* __restrict__ bptr,
                         int writeConf)
{
    __shared__ uint32_t mw[NK / 32];

    const int lane = threadIdx.x & 31;
    const int w    = threadIdx.x >> 5;
    const int row0 = blockIdx.x * 8;
    const int b    = row0 >> 9;

    if (threadIdx.x < NK / 32)
        mw[threadIdx.x] = maskbits[b * (NK / 32) + threadIdx.x];
    __syncthreads();

    const int row = row0 + w;
    float4* rp4 = (float4*)(attn + (size_t)row * NK);

    float x[16];
#pragma unroll
    for (int i = 0; i < 4; i++) {
        float4 v = rp4[i * 32 + lane];
        const int cbase = (i * 32 + lane) * 4;
        const uint32_t nib = (mw[cbase >> 5] >> (cbase & 31)) & 0xF;
        x[4 * i + 0] = (nib & 1) ? NEG_INF : v.x;
        x[4 * i + 1] = (nib & 2) ? NEG_INF : v.y;
        x[4 * i + 2] = (nib & 4) ? NEG_INF : v.z;
        x[4 * i + 3] = (nib & 8) ? NEG_INF : v.w;
    }

    float m = x[0];
#pragma unroll
    for (int i = 1; i < 16; i++) m = fmaxf(m, x[i]);
#pragma unroll
    for (int o = 16; o > 0; o >>= 1)
        m = fmaxf(m, __shfl_xor_sync(0xffffffffu, m, o));

    float e[16];
    float sum = 0.0f;
#pragma unroll
    for (int i = 0; i < 16; i++) {
        e[i] = __expf(x[i] - m);
        sum += e[i];
    }
#pragma unroll
    for (int o = 16; o > 0; o >>= 1)
        sum += __shfl_xor_sync(0xffffffffu, sum, o);

    const float inv = 1.0f / sum;
#pragma unroll
    for (int i = 0; i < 4; i++) {
        float4 o;
        o.x = e[4 * i + 0] * inv;
        o.y = e[4 * i + 1] * inv;
        o.z = e[4 * i + 2] * inv;
        o.w = e[4 * i + 3] * inv;
        rp4[i * 32 + lane] = o;
    }

    if (lane == 0 && writeConf) {
        const float lse  = m + __logf(sum);
        const float temp = *tptr;
        const float bia  = *bptr;
        const float z    = (lse + bia) * temp;
        conf[row] = 1.0f / (1.0f + __expf(-z));
    }
}

// ---------------------------------------------------------------------------
extern "C" void kernel_launch(void* const* d_in, const int* in_sizes, int n_in,
                              void* d_out, int out_size)
{
    const float* q  = (const float*)d_in[0];
    const float* k  = (const float*)d_in[1];
    const float* t  = (const float*)d_in[2];
    const float* bi = (const float*)d_in[3];

    float* attn = (float*)d_out;
    const long long attnElems = (long long)NB * NQ * NK;       // 8388608
    const int writeConf = (out_size >= attnElems + NB * NQ) ? 1 : 0;
    float* conf = attn + attnElems;

    static int smemSet = 0;
    if (!smemSet) {
        cudaFuncSetAttribute(gemm_hmma_kernel,
                             cudaFuncAttributeMaxDynamicSharedMemorySize, SMEM_BYTES);
        smemSet = 1;
    }

    static __half *Qh = nullptr, *Ql = nullptr, *Kh = nullptr, *Kl = nullptr;
    static uint32_t* Mb = nullptr;
    if (!Qh) {
        cudaGetSymbolAddress((void**)&Qh, g_Qh);
        cudaGetSymbolAddress((void**)&Ql, g_Ql);
        cudaGetSymbolAddress((void**)&Kh, g_Kh);
        cudaGetSymbolAddress((void**)&Kl, g_Kl);
        cudaGetSymbolAddress((void**)&Mb, g_mask);
    }

    convert_kernel<<<ELEMS / (256 * 8), 256>>>(q, Qh, Ql);
    convert_kernel<<<ELEMS / (256 * 8), 256>>>(k, Kh, Kl);
    mask_kernel<<<NB, 512>>>(k, Mb);

    dim3 grid(NK / BN, NQ / BM, NB);        // (4, 4, 32)
    gemm_hmma_kernel<<<grid, THREADS, SMEM_BYTES>>>(attn);

    softmax_mask_kernel<<<(NB * NQ) / 8, 256>>>(attn, conf, Mb, t, bi, writeConf);
}

// round 17
// speedup vs baseline: 1.2865x; 1.0809x over previous
#include <cuda_runtime.h>
#include <cuda_fp16.h>
#include <cstdint>

// Problem shape (fixed): B=32, Q=512, K=512, D=1024
#define NB   32
#define NQ   512
#define NK   512
#define ND   1024

#define BM 128
#define BN 128
#define KC 32                  // K elements per chunk
#define NCHUNK (ND / KC)       // 32
#define THREADS 256
#define NSTAGE 3

// SMEM tile geometry: fp16 plane = 128 rows x 32 halfs = 64B rows, XOR-swizzled
// (no padding). swizzle: 16B-col c' = c ^ ((row>>1)&3)  -> conflict-free
// for ldmatrix (8 consecutive rows, fixed c) and for cp.async stores.
#define ROWB    64
#define PLANE_B (128 * ROWB)          // 8192
#define STAGE_B (4 * PLANE_B)         // 32768 (Ahi | Alo | Bhi | Blo)
#define SMEM_BYTES (NSTAGE * STAGE_B) // 98304 -> 2 CTAs/SM

#define NEG_INF  (__int_as_float(0xff800000))
#define INV2048  4.8828125e-4f

// ---------------------------------------------------------------------------
// device scratch (no allocation in kernel_launch)
// ---------------------------------------------------------------------------
#define ELEMS (NB * NQ * ND)   // 16777216 per tensor
__device__ __align__(16) __half g_Qh[ELEMS];
__device__ __align__(16) __half g_Ql[ELEMS];
__device__ __align__(16) __half g_Kh[ELEMS];
__device__ __align__(16) __half g_Kl[ELEMS];
__device__ uint32_t g_mask[NB * (NK / 32)];    // key-mask bitmaps

// ---------------------------------------------------------------------------
// helpers
// ---------------------------------------------------------------------------
__device__ __forceinline__ uint32_t smem_u32(const void* p) {
    uint32_t a;
    asm("{ .reg .u64 t; cvta.to.shared.u64 t, %1; cvt.u32.u64 %0, t; }"
        : "=r"(a) : "l"(p));
    return a;
}

#define CP_ASYNC16(dst, src) \
    asm volatile("cp.async.cg.shared.global [%0], [%1], 16;" :: "r"(dst), "l"(src))
#define CP_COMMIT() asm volatile("cp.async.commit_group;" ::: "memory")
#define CP_WAIT1()  asm volatile("cp.async.wait_group 1;" ::: "memory")

#define LDSM4(r0, r1, r2, r3, a)                                                \
    asm volatile("ldmatrix.sync.aligned.m8n8.x4.shared.b16 {%0,%1,%2,%3}, [%4];" \
                 : "=r"(r0), "=r"(r1), "=r"(r2), "=r"(r3) : "r"(a))

// fp32-accumulate MMA (main hi x hi pass)
#define MMA_F32(c, a0, a1, a2, a3, b0, b1)                                       \
    asm volatile(                                                                \
        "mma.sync.aligned.m16n8k16.row.col.f32.f16.f16.f32 "                     \
        "{%0,%1,%2,%3}, {%4,%5,%6,%7}, {%8,%9}, {%0,%1,%2,%3};"                  \
        : "+f"((c)[0]), "+f"((c)[1]), "+f"((c)[2]), "+f"((c)[3])                 \
        : "r"(a0), "r"(a1), "r"(a2), "r"(a3), "r"(b0), "r"(b1))

// fp16-accumulate MMA (correction passes, accumulated unscaled)
#define MMA_F16(c, a0, a1, a2, a3, b0, b1)                                       \
    asm volatile(                                                                \
        "mma.sync.aligned.m16n8k16.row.col.f16.f16.f16.f16 "                     \
        "{%0,%1}, {%2,%3,%4,%5}, {%6,%7}, {%0,%1};"                              \
        : "+r"((c)[0]), "+r"((c)[1])                                             \
        : "r"(a0), "r"(a1), "r"(a2), "r"(a3), "r"(b0), "r"(b1))

// ---------------------------------------------------------------------------
// Kernel 0: streaming fp32 -> (hi fp16, lo' fp16 = (x-hi)*2048) split.
// ---------------------------------------------------------------------------
__global__ __launch_bounds__(256)
void convert_kernel(const float* __restrict__ src,
                    __half* __restrict__ hi,
                    __half* __restrict__ lo)
{
    const size_t i = ((size_t)blockIdx.x * 256 + threadIdx.x) * 8;
    float4 a = *(const float4*)(src + i);
    float4 b = *(const float4*)(src + i + 4);

    __half2 h0 = __floats2half2_rn(a.x, a.y);
    __half2 h1 = __floats2half2_rn(a.z, a.w);
    __half2 h2 = __floats2half2_rn(b.x, b.y);
    __half2 h3 = __floats2half2_rn(b.z, b.w);

    __half2 l0 = __floats2half2_rn((a.x - __low2float(h0)) * 2048.0f,
                                   (a.y - __high2float(h0)) * 2048.0f);
    __half2 l1 = __floats2half2_rn((a.z - __low2float(h1)) * 2048.0f,
                                   (a.w - __high2float(h1)) * 2048.0f);
    __half2 l2 = __floats2half2_rn((b.x - __low2float(h2)) * 2048.0f,
                                   (b.y - __high2float(h2)) * 2048.0f);
    __half2 l3 = __floats2half2_rn((b.z - __low2float(h3)) * 2048.0f,
                                   (b.w - __high2float(h3)) * 2048.0f);

    *(uint4*)(hi + i) = make_uint4(*(uint32_t*)&h0, *(uint32_t*)&h1,
                                   *(uint32_t*)&h2, *(uint32_t*)&h3);
    *(uint4*)(lo + i) = make_uint4(*(uint32_t*)&l0, *(uint32_t*)&l1,
                                   *(uint32_t*)&l2, *(uint32_t*)&l3);
}

// ---------------------------------------------------------------------------
// Kernel 0b: key-mask bitmap (keys[b,k,0] == 0)
// ---------------------------------------------------------------------------
__global__ __launch_bounds__(512)
void mask_kernel(const float* __restrict__ keys, uint32_t* __restrict__ mask)
{
    const int b = blockIdx.x;
    const int k = threadIdx.x;
    const float k0 = __ldg(keys + (size_t)b * NK * ND + (size_t)k * ND);
    const uint32_t bits = __ballot_sync(0xffffffffu, k0 == 0.0f);
    if ((k & 31) == 0) mask[b * (NK / 32) + (k >> 5)] = bits;
}

// ---------------------------------------------------------------------------
// Kernel 1: batched NT GEMM, fp32 emulated via fp16 mma.sync (3 passes).
// 128x128 CTA tile, 256 threads / 8 warps, warp tile 64x32,
// KC=32 chunks, 3-stage cp.async pipeline, swizzled SMEM (96KB),
// TWO CTAs co-resident per SM so barrier windows overlap across CTAs.
// ---------------------------------------------------------------------------
__global__ __launch_bounds__(THREADS, 2)
void gemm_hmma_kernel(float* __restrict__ C)
{
    extern __shared__ __align__(16) char smem[];
    const uint32_t sb = smem_u32(smem);

    const int tid  = threadIdx.x;
    const int wid  = tid >> 5;
    const int lane = tid & 31;
    const int gid  = lane >> 2;
    const int tig  = lane & 3;

    const int wm = wid & 1;           // 0..1 -> 64-row band
    const int wn = wid >> 1;          // 0..3 -> 32-col band

    const int b  = blockIdx.z;
    const int m0 = blockIdx.y * BM;
    const int n0 = blockIdx.x * BN;

    const size_t Aoff = (size_t)b * NQ * ND + (size_t)m0 * ND;
    const size_t Boff = (size_t)b * NK * ND + (size_t)n0 * ND;
    float* Cb = C + (size_t)b * NQ * NK;

    const __half* pb[4] = { g_Qh + Aoff, g_Ql + Aoff, g_Kh + Boff, g_Kl + Boff };

    // cp.async geometry: 8 issues/thread/stage (2 per plane).
    // unit u = i*256 + tid; plane = u>>9; idx = u&511; row = idx>>2; c = idx&3.
    // ldmatrix per-lane addressing (swizzle factor invariant across mt/ntp
    // because 16-row steps leave ((row>>1)&3) unchanged)
    const int arow_lane = wm * 64 + (lane & 15);
    const int acol      = (lane >> 4);              // 16B col 0/1
    const uint32_t sA   = (uint32_t)((arow_lane >> 1) & 3);
    const int brow_lane = wn * 32 + ((lane >> 4) * 8) + (lane & 7);
    const int bcol      = ((lane >> 3) & 1);
    const uint32_t sB   = (uint32_t)((brow_lane >> 1) & 3);

    float acc[4][4][4];
    uint32_t acc16[4][4][2];
#pragma unroll
    for (int i = 0; i < 4; i++)
#pragma unroll
        for (int j = 0; j < 4; j++) {
#pragma unroll
            for (int k = 0; k < 4; k++) acc[i][j][k] = 0.0f;
            acc16[i][j][0] = 0u; acc16[i][j][1] = 0u;
        }

    auto issue_stage = [&](int kc, int buf) {
        const uint32_t sdst = sb + buf * STAGE_B;
#pragma unroll
        for (int i = 0; i < 8; i++) {
            const int u    = i * 256 + tid;
            const int p    = u >> 9;
            const int idx  = u & 511;
            const int row  = idx >> 2;
            const int c    = idx & 3;
            const int csw  = c ^ ((row >> 1) & 3);
            const __half* src = pb[p] + (size_t)row * ND + kc * KC + c * 8;
            const uint32_t dst = sdst + p * PLANE_B + row * ROWB + csw * 16;
            CP_ASYNC16(dst, src);
        }
    };

    issue_stage(0, 0); CP_COMMIT();
    issue_stage(1, 1); CP_COMMIT();

    for (int kc = 0; kc < NCHUNK; kc++) {
        const int buf = kc % NSTAGE;
        CP_WAIT1();
        __syncthreads();

        if (kc + 2 < NCHUNK) issue_stage(kc + 2, (kc + 2) % NSTAGE);
        CP_COMMIT();

        const uint32_t st   = sb + buf * STAGE_B;
        const uint32_t stA  = st;                    // Ahi
        const uint32_t stAl = st + PLANE_B;          // Alo'
        const uint32_t stB  = st + 2 * PLANE_B;      // Bhi
        const uint32_t stBl = st + 3 * PLANE_B;      // Blo'

#pragma unroll
        for (int ks = 0; ks < 2; ks++) {
            const uint32_t ca = (uint32_t)((acol + ks * 2) ^ sA) * 16;
            const uint32_t cb = (uint32_t)((bcol + ks * 2) ^ sB) * 16;

            // ---- batch ALL fragment loads for this k-step up front ----
            uint32_t ah[4][4], al[4][4], bh[4][2], bl[4][2];
#pragma unroll
            for (int mt = 0; mt < 4; mt++) {
                const uint32_t a = stA + (arow_lane + mt * 16) * ROWB + ca;
                LDSM4(ah[mt][0], ah[mt][1], ah[mt][2], ah[mt][3], a);
            }
#pragma unroll
            for (int ntp = 0; ntp < 2; ntp++) {
                const uint32_t a = stB + (brow_lane + ntp * 16) * ROWB + cb;
                LDSM4(bh[2 * ntp][0], bh[2 * ntp][1],
                      bh[2 * ntp + 1][0], bh[2 * ntp + 1][1], a);
            }
#pragma unroll
            for (int ntp = 0; ntp < 2; ntp++) {
                const uint32_t a = stBl + (brow_lane + ntp * 16) * ROWB + cb;
                LDSM4(bl[2 * ntp][0], bl[2 * ntp][1],
                      bl[2 * ntp + 1][0], bl[2 * ntp + 1][1], a);
            }
#pragma unroll
            for (int mt = 0; mt < 4; mt++) {
                const uint32_t a = stAl + (arow_lane + mt * 16) * ROWB + ca;
                LDSM4(al[mt][0], al[mt][1], al[mt][2], al[mt][3], a);
            }

            // pass 1: hi x hi -> fp32 acc
#pragma unroll
            for (int mt = 0; mt < 4; mt++)
#pragma unroll
                for (int nt = 0; nt < 4; nt++)
                    MMA_F32(acc[mt][nt], ah[mt][0], ah[mt][1], ah[mt][2], ah[mt][3],
                            bh[nt][0], bh[nt][1]);

            // pass 2: hi_a x lo'_b -> fp16 acc (unscaled)
#pragma unroll
            for (int mt = 0; mt < 4; mt++)
#pragma unroll
                for (int nt = 0; nt < 4; nt++)
                    MMA_F16(acc16[mt][nt], ah[mt][0], ah[mt][1], ah[mt][2], ah[mt][3],
                            bl[nt][0], bl[nt][1]);

            // pass 3: lo'_a x hi_b -> fp16 acc
#pragma unroll
            for (int mt = 0; mt < 4; mt++)
#pragma unroll
                for (int nt = 0; nt < 4; nt++)
                    MMA_F16(acc16[mt][nt], al[mt][0], al[mt][1], al[mt][2], al[mt][3],
                            bh[nt][0], bh[nt][1]);
        }
        __syncthreads();
    }

    // epilogue: combine fp32 main + fp16 correction * 2^-11
#pragma unroll
    for (int mt = 0; mt < 4; mt++) {
        const int mrow = m0 + wm * 64 + mt * 16 + gid;
#pragma unroll
        for (int nt = 0; nt < 4; nt++) {
            const int col = n0 + wn * 32 + nt * 8 + tig * 2;
            float2 c0 = __half22float2(*reinterpret_cast<__half2*>(&acc16[mt][nt][0]));
            float2 c1 = __half22float2(*reinterpret_cast<__half2*>(&acc16[mt][nt][1]));
            float* cp0 = Cb + (size_t)mrow * NK + col;
            float* cp1 = Cb + (size_t)(mrow + 8) * NK + col;
            *(float2*)cp0 = make_float2(fmaf(c0.x, INV2048, acc[mt][nt][0]),
                                        fmaf(c0.y, INV2048, acc[mt][nt][1]));
            *(float2*)cp1 = make_float2(fmaf(c1.x, INV2048, acc[mt][nt][2]),
                                        fmaf(c1.y, INV2048, acc[mt][nt][3]));
        }
    }
}

// ---------------------------------------------------------------------------
// Kernel 2: fused key-mask + softmax + logsumexp->sigmoid confidence.
// One warp per (b,q) row; mask from precomputed bitmap; float4 row I/O.
// ---------------------------------------------------------------------------
__global__ __launch_bounds__(256)
void softmax_mask_kernel(float* __restrict__ attn,
                         float* __restrict__ conf,
                         const uint32_t* __restrict__ maskbits,
                         const float* __restrict__ tptr,
                         const float* __restrict__ bptr,
                         int writeConf)
{
    __shared__ uint32_t mw[NK / 32];

    const int lane = threadIdx.x & 31;
    const int w    = threadIdx.x >> 5;
    const int row0 = blockIdx.x * 8;
    const int b    = row0 >> 9;

    if (threadIdx.x < NK / 32)
        mw[threadIdx.x] = maskbits[b * (NK / 32) + threadIdx.x];
    __syncthreads();

    const int row = row0 + w;
    float4* rp4 = (float4*)(attn + (size_t)row * NK);

    float x[16];
#pragma unroll
    for (int i = 0; i < 4; i++) {
        float4 v = rp4[i * 32 + lane];
        const int cbase = (i * 32 + lane) * 4;
        const uint32_t nib = (mw[cbase >> 5] >> (cbase & 31)) & 0xF;
        x[4 * i + 0] = (nib & 1) ? NEG_INF : v.x;
        x[4 * i + 1] = (nib & 2) ? NEG_INF : v.y;
        x[4 * i + 2] = (nib & 4) ? NEG_INF : v.z;
        x[4 * i + 3] = (nib & 8) ? NEG_INF : v.w;
    }

    float m = x[0];
#pragma unroll
    for (int i = 1; i < 16; i++) m = fmaxf(m, x[i]);
#pragma unroll
    for (int o = 16; o > 0; o >>= 1)
        m = fmaxf(m, __shfl_xor_sync(0xffffffffu, m, o));

    float e[16];
    float sum = 0.0f;
#pragma unroll
    for (int i = 0; i < 16; i++) {
        e[i] = __expf(x[i] - m);
        sum += e[i];
    }
#pragma unroll
    for (int o = 16; o > 0; o >>= 1)
        sum += __shfl_xor_sync(0xffffffffu, sum, o);

    const float inv = 1.0f / sum;
#pragma unroll
    for (int i = 0; i < 4; i++) {
        float4 o;
        o.x = e[4 * i + 0] * inv;
        o.y = e[4 * i + 1] * inv;
        o.z = e[4 * i + 2] * inv;
        o.w = e[4 * i + 3] * inv;
        rp4[i * 32 + lane] = o;
    }

    if (lane == 0 && writeConf) {
        const float lse  = m + __logf(sum);
        const float temp = *tptr;
        const float bia  = *bptr;
        const float z    = (lse + bia) * temp;
        conf[row] = 1.0f / (1.0f + __expf(-z));
    }
}

// ---------------------------------------------------------------------------
extern "C" void kernel_launch(void* const* d_in, const int* in_sizes, int n_in,
                              void* d_out, int out_size)
{
    const float* q  = (const float*)d_in[0];
    const float* k  = (const float*)d_in[1];
    const float* t  = (const float*)d_in[2];
    const float* bi = (const float*)d_in[3];

    float* attn = (float*)d_out;
    const long long attnElems = (long long)NB * NQ * NK;       // 8388608
    const int writeConf = (out_size >= attnElems + NB * NQ) ? 1 : 0;
    float* conf = attn + attnElems;

    static int smemSet = 0;
    if (!smemSet) {
        cudaFuncSetAttribute(gemm_hmma_kernel,
                             cudaFuncAttributeMaxDynamicSharedMemorySize, SMEM_BYTES);
        smemSet = 1;
    }

    static __half *Qh = nullptr, *Ql = nullptr, *Kh = nullptr, *Kl = nullptr;
    static uint32_t* Mb = nullptr;
    if (!Qh) {
        cudaGetSymbolAddress((void**)&Qh, g_Qh);
        cudaGetSymbolAddress((void**)&Ql, g_Ql);
        cudaGetSymbolAddress((void**)&Kh, g_Kh);
        cudaGetSymbolAddress((void**)&Kl, g_Kl);
        cudaGetSymbolAddress((void**)&Mb, g_mask);
    }

    convert_kernel<<<ELEMS / (256 * 8), 256>>>(q, Qh, Ql);
    convert_kernel<<<ELEMS / (256 * 8), 256>>>(k, Kh, Kl);
    mask_kernel<<<NB, 512>>>(k, Mb);

    dim3 grid(NK / BN, NQ / BM, NB);        // (4, 4, 32)
    gemm_hmma_kernel<<<grid, THREADS, SMEM_BYTES>>>(attn);

    softmax_mask_kernel<<<(NB * NQ) / 8, 256>>>(attn, conf, Mb, t, bi, writeConf);
}